// round 9
// baseline (speedup 1.0000x reference)
#include <cuda_runtime.h>
#include <math.h>

// HG2Vec fused loss, v9: cp.async producer/consumer pipeline through SMEM.
//
// Per position: 27 UNIQUE rows (1 tgt + 10 ctx_in + 10 ctx_out + 6 info),
// 300 f32 each = 32.4 KB, staged into a double-buffered SMEM tile with
// cp.async.cg (16B copies, no destination registers -> prefetch depth is
// decoupled from register pressure / occupancy). While position k is computed
// from SMEM (LDS.128), position k+1's tile is in flight. Rows are fetched
// ONCE per position (v6 fetched shared rows 5x via L1).
//
// 5 warps/CTA, warp w computes contexts {2w, 2w+1}: 14 accumulators,
// scattered 16-value warp reduction (31 shfl), fast softplus (MUFU).
// Grid 444 = 148 SMs * 3 resident CTAs (SMEM-limited: 2x32.4 KB/CTA).
// Last-block-done deterministic reduction, ticket self-resets (graph-safe).

#define DIM        300
#define ROWBYTES   1200
#define NPOS       16384          // B*L
#define GRID       444            // 148 SMs * 3 resident CTAs
#define THREADS    160            // 5 warps
#define NROWS      27             // unique rows per position
#define NCPY       (NROWS * 75)   // 2025 16-byte copies per position
#define BUFBYTES   (NROWS * ROWBYTES)      // 32400
#define IDXOFF     (2 * BUFBYTES)          // idx slots after the 2 data buffers
#define SMEM_TOTAL (IDXOFF + 2 * 32 * 4)   // + 2 x 32 ints

__device__ float        g_partial[GRID];
__device__ unsigned int g_ticket = 0;

#define CP_ASYNC16(DST, SRC) \
    asm volatile("cp.async.cg.shared.global [%0], [%1], 16;" :: "r"(DST), "l"(SRC) : "memory")
#define CP_COMMIT()  asm volatile("cp.async.commit_group;" ::: "memory")
#define CP_WAIT1()   asm volatile("cp.async.wait_group 1;" ::: "memory")
#define CP_WAIT0()   asm volatile("cp.async.wait_group 0;" ::: "memory")

// scattered 16-value warp reduction (31 shfl) + in-place loss term.
// v[16] = {sc0, sc1, ai[0..11], 0, 0}; sum of value q lands on lanes {2q, 2q+1}.
__device__ __forceinline__ float reduce_eval(
    float sc0, float sc1, const float* ai, int lane,
    float t_pre, float t_sgn, float t_wt)
{
    float v0[8], v1[4], v2[2], v3;
    {
        float a, b;
        a = sc0   + __shfl_xor_sync(0xffffffffu, sc0,   16);
        b = ai[6] + __shfl_xor_sync(0xffffffffu, ai[6], 16);
        v0[0] = (lane & 16) ? b : a;
        a = sc1   + __shfl_xor_sync(0xffffffffu, sc1,   16);
        b = ai[7] + __shfl_xor_sync(0xffffffffu, ai[7], 16);
        v0[1] = (lane & 16) ? b : a;
#pragma unroll
        for (int q = 0; q < 4; q++) {
            a = ai[q]     + __shfl_xor_sync(0xffffffffu, ai[q],     16);
            b = ai[q + 8] + __shfl_xor_sync(0xffffffffu, ai[q + 8], 16);
            v0[2 + q] = (lane & 16) ? b : a;
        }
        a = ai[4] + __shfl_xor_sync(0xffffffffu, ai[4], 16);
        v0[6] = (lane & 16) ? 0.f : a;
        a = ai[5] + __shfl_xor_sync(0xffffffffu, ai[5], 16);
        v0[7] = (lane & 16) ? 0.f : a;
    }
#pragma unroll
    for (int q = 0; q < 4; q++) {
        const float a = v0[q]     + __shfl_xor_sync(0xffffffffu, v0[q],     8);
        const float b = v0[q + 4] + __shfl_xor_sync(0xffffffffu, v0[q + 4], 8);
        v1[q] = (lane & 8) ? b : a;
    }
#pragma unroll
    for (int q = 0; q < 2; q++) {
        const float a = v1[q]     + __shfl_xor_sync(0xffffffffu, v1[q],     4);
        const float b = v1[q + 2] + __shfl_xor_sync(0xffffffffu, v1[q + 2], 4);
        v2[q] = (lane & 4) ? b : a;
    }
    {
        const float a = v2[0] + __shfl_xor_sync(0xffffffffu, v2[0], 2);
        const float b = v2[1] + __shfl_xor_sync(0xffffffffu, v2[1], 2);
        v3 = (lane & 2) ? b : a;
    }
    v3 += __shfl_xor_sync(0xffffffffu, v3, 1);

    const float x = fminf(fmaxf(v3 * t_pre, -10.f), 10.f) * t_sgn;
    return __logf(1.f + __expf(-x)) * t_wt;
}

__global__ __launch_bounds__(THREADS) void hg2vec_fused(
    const int*   __restrict__ pos_u,
    const int*   __restrict__ pos_v,
    const int*   __restrict__ info_v,
    const float* __restrict__ W_in,
    const float* __restrict__ W_out,
    const float* __restrict__ cmask,
    const float* __restrict__ sig_mask,
    const float* __restrict__ score_mask,
    float*       __restrict__ out)
{
    extern __shared__ char smem[];
    __shared__ float wloss[5];
    __shared__ bool  amLast;

    const unsigned sbase = (unsigned)__cvta_generic_to_shared(smem);
    const int tid  = threadIdx.x;
    const int w    = tid >> 5;
    const int lane = tid & 31;

    const char* __restrict__ Win_b  = (const char*)W_in;
    const char* __restrict__ Wout_b = (const char*)W_out;

    // ---- per-lane term coefficients; value index k = lane>>1 ----
    const int kk = lane >> 1;
    float t_pre = 1.f, t_sgn = 1.f, t_wt = 0.f;
    if (((lane & 1) == 0) && kk < 14) {
        if (kk < 2) { t_pre = cmask[w * 2 + kk]; t_sgn = 1.f; t_wt = 1.f; }
        else {
            const int i = (kk - 2) % 6;
            t_sgn = sig_mask[i];
            t_wt  = score_mask[i];
        }
    }

    // ---- idx staging: slot s holds {pu, pv[0..9], iv[0..5]} for one position ----
    int* const idx0 = (int*)(smem + IDXOFF);
    int* const idx1 = (int*)(smem + IDXOFF + 128);
#define STAGE_IDX(Q, SLOTP)                                                  \
    do {                                                                     \
        if (tid < 17) {                                                      \
            const int ps_ = ((Q) < NPOS) ? (Q) : (NPOS - 1);                 \
            int v_;                                                          \
            if (tid == 0)       v_ = pos_u[ps_];                             \
            else if (tid <= 10) v_ = pos_v[ps_ * 10 + (tid - 1)];            \
            else                v_ = info_v[ps_ * 6 + (tid - 11)];           \
            (SLOTP)[tid] = v_;                                               \
        }                                                                    \
    } while (0)

    // ---- producer: issue 2025 cp.async 16B copies for one position ----
    // rows: 0 = W_out[pu]; 1..10 = W_in[pv]; 11..20 = W_out[pv]; 21..26 = W_in[iv]
#define PRODUCE(BUF, SLOTP)                                                  \
    do {                                                                     \
        const unsigned dbase_ = sbase + (unsigned)(BUF) * BUFBYTES;          \
        _Pragma("unroll")                                                    \
        for (int k_ = 0; k_ < 13; k_++) {                                    \
            const int n_ = tid + k_ * THREADS;                               \
            if (n_ < NCPY) {                                                 \
                const int row_  = n_ / 75;                                   \
                const int col_  = n_ - row_ * 75;                            \
                const int slot_ = (row_ <= 10) ? row_ : row_ - 10;           \
                const int idx_  = (SLOTP)[slot_];                            \
                const bool in_  = (row_ >= 21) || (row_ >= 1 && row_ <= 10); \
                const char* src_ = (in_ ? Win_b : Wout_b)                    \
                                 + (long)idx_ * ROWBYTES + col_ * 16;        \
                const unsigned dst_ = dbase_ + row_ * ROWBYTES + col_ * 16;  \
                CP_ASYNC16(dst_, src_);                                      \
            }                                                                \
        }                                                                    \
    } while (0)

    float acc_loss = 0.f;
    int p   = blockIdx.x;
    int cur = 0;

    // ---- prime the pipeline ----
    STAGE_IDX(p, idx0);
    __syncthreads();
    PRODUCE(0, idx0);
    CP_COMMIT();
    STAGE_IDX(p + GRID, idx1);
    __syncthreads();           // idx1 visible before first loop iteration

    while (p < NPOS) {
        const int pn = p + GRID;
        int* const slot_cur = cur ? idx1 : idx0;
        int* const slot_nxt = cur ? idx0 : idx1;

        if (pn < NPOS) {
            PRODUCE(cur ^ 1, slot_nxt);        // prefetch position pn
            CP_COMMIT();
            STAGE_IDX(pn + GRID, slot_cur);    // idx for p+2*GRID into freed slot
            CP_WAIT1();                        // current buffer's group done
        } else {
            CP_WAIT0();
        }
        __syncthreads();                       // data[cur] visible to all warps

        // ---- compute position p from SMEM ----
        {
            const char* db  = smem + cur * BUFBYTES;
            const char* tR  = db;
            const char* a0R = db + (1  + 2 * w) * ROWBYTES;
            const char* a1R = db + (2  + 2 * w) * ROWBYTES;
            const char* b0R = db + (11 + 2 * w) * ROWBYTES;
            const char* b1R = db + (12 + 2 * w) * ROWBYTES;
            const char* fR  = db + 21 * ROWBYTES;

            float sc0 = 0.f, sc1 = 0.f;
            float ai[12];
#pragma unroll
            for (int q = 0; q < 12; q++) ai[q] = 0.f;

#pragma unroll
            for (int jj = 0; jj < 3; jj++) {
                const int j = lane + jj * 32;
                if (j < 75) {
                    const unsigned jb = (unsigned)j * 16u;
                    const float4 t4 = *(const float4*)(tR  + jb);
                    const float4 a0 = *(const float4*)(a0R + jb);
                    const float4 a1 = *(const float4*)(a1R + jb);
                    const float4 b0 = *(const float4*)(b0R + jb);
                    const float4 b1 = *(const float4*)(b1R + jb);
                    float4 f4[6];
#pragma unroll
                    for (int i = 0; i < 6; i++)
                        f4[i] = *(const float4*)(fR + i * ROWBYTES + jb);

                    sc0 += a0.x * t4.x + a0.y * t4.y + a0.z * t4.z + a0.w * t4.w;
                    sc1 += a1.x * t4.x + a1.y * t4.y + a1.z * t4.z + a1.w * t4.w;
#pragma unroll
                    for (int i = 0; i < 6; i++) {
                        ai[i]     += b0.x * f4[i].x + b0.y * f4[i].y
                                   + b0.z * f4[i].z + b0.w * f4[i].w;
                        ai[6 + i] += b1.x * f4[i].x + b1.y * f4[i].y
                                   + b1.z * f4[i].z + b1.w * f4[i].w;
                    }
                }
            }

            acc_loss += reduce_eval(sc0, sc1, ai, lane, t_pre, t_sgn, t_wt);
        }

        __syncthreads();       // all warps done reading data[cur] before overwrite
        cur ^= 1;
        p = pn;
    }

    // ---- block reduction ----
#pragma unroll
    for (int off = 16; off; off >>= 1)
        acc_loss += __shfl_xor_sync(0xffffffffu, acc_loss, off);
    if (lane == 0) wloss[w] = acc_loss;
    __syncthreads();

    if (tid == 0) {
        float s = wloss[0] + wloss[1] + wloss[2] + wloss[3] + wloss[4];
        g_partial[blockIdx.x] = s;
        __threadfence();
        unsigned t = atomicAdd(&g_ticket, 1u);
        amLast = (t == GRID - 1);
    }
    __syncthreads();

    // ---- last block: deterministic fixed-order final sum ----
    if (amLast) {
        __shared__ float fs[THREADS];
        float v = 0.f;
        for (int i = tid; i < GRID; i += THREADS)
            v += __ldcg(&g_partial[i]);
        fs[tid] = v;
        __syncthreads();
#pragma unroll
        for (int st = 128; st; st >>= 1) {
            if (tid < st && tid + st < THREADS)
                fs[tid] += fs[tid + st];
            __syncthreads();
        }
        if (tid == 0) {
            out[0] = fs[0];
            g_ticket = 0;            // reset for next graph replay
            __threadfence();
        }
    }
}

extern "C" void kernel_launch(void* const* d_in, const int* in_sizes, int n_in,
                              void* d_out, int out_size)
{
    const int*   pos_u  = (const int*)  d_in[0];
    const int*   pos_v  = (const int*)  d_in[1];
    const int*   info_v = (const int*)  d_in[2];
    const float* W_in   = (const float*)d_in[3];
    const float* W_out  = (const float*)d_in[4];
    const float* cmask  = (const float*)d_in[5];
    const float* sigm   = (const float*)d_in[6];
    const float* smask  = (const float*)d_in[7];

    cudaFuncSetAttribute(hg2vec_fused,
                         cudaFuncAttributeMaxDynamicSharedMemorySize, SMEM_TOTAL);
    hg2vec_fused<<<GRID, THREADS, SMEM_TOTAL>>>(pos_u, pos_v, info_v, W_in, W_out,
                                                cmask, sigm, smask, (float*)d_out);
}

// round 10
// speedup vs baseline: 1.2765x; 1.2765x over previous
#include <cuda_runtime.h>
#include <math.h>

// HG2Vec fused loss, v10: hybrid SMEM(shared rows) + register(private rows) pipeline.
//
// Per position, per warp w (contexts 2w, 2w+1), the 11 operand rows split:
//   shared across all 5 warps : t = W_out[pu], f[0..5] = W_in[iv]   (7 rows)
//   private to the warp       : a0,a1 = W_in[pv], b0,b1 = W_out[pv] (4 rows)
// Shared rows are staged position-ahead into a double-buffered SMEM tile via
// cp.async.cg (8.4 KB/position): latency structurally hidden, fetched once
// instead of 5x. Private rows use v6's register pipeline (chunk0 of the next
// position preloaded before the butterfly). Freeing the 24-reg f-buffer drops
// the footprint so 5 CTAs/SM fit: 25 warps/SM resident.
//
// Grid 740 = 148 SMs * 5 CTAs, one persistent wave. Scattered 16-value warp
// reduction (31 shfl), fast softplus (MUFU). Last-block-done deterministic
// reduction, ticket self-resets (graph-safe).

#define DIM       300
#define ROWBYTES  1200
#define NPOS      16384           // B*L
#define GRID      740             // 148 SMs * 5 resident CTAs
#define THREADS   160             // 5 warps = 1 position
#define SHROWS    7               // t + f[0..5]
#define SHBUF     (SHROWS * ROWBYTES)   // 8400 B per stage
#define NCPY      (SHROWS * 75)         // 525 16-byte copies per position

__device__ float        g_partial[GRID];
__device__ unsigned int g_ticket = 0;

#define CP_ASYNC16(DST, SRC) \
    asm volatile("cp.async.cg.shared.global [%0], [%1], 16;" :: "r"(DST), "l"(SRC) : "memory")
#define CP_COMMIT()  asm volatile("cp.async.commit_group;" ::: "memory")
#define CP_WAIT1()   asm volatile("cp.async.wait_group 1;" ::: "memory")
#define CP_WAIT0()   asm volatile("cp.async.wait_group 0;" ::: "memory")

// load the 4 private rows' chunk at byte offset JB
#define AB_LOAD(JB)                                                          \
    do {                                                                     \
        a0 = *(const float4*)(Win_b  + pvo0 + (JB));                         \
        a1 = *(const float4*)(Win_b  + pvo1 + (JB));                         \
        b0 = *(const float4*)(Wout_b + pvo0 + (JB));                         \
        b1 = *(const float4*)(Wout_b + pvo1 + (JB));                         \
    } while (0)

// accumulate one chunk: t/f from SMEM tile (tf), a/b from registers
#define TF_CHUNK(JB)                                                         \
    do {                                                                     \
        const float4 t4 = *(const float4*)(tf + (JB));                       \
        sc0 += a0.x * t4.x + a0.y * t4.y + a0.z * t4.z + a0.w * t4.w;        \
        sc1 += a1.x * t4.x + a1.y * t4.y + a1.z * t4.z + a1.w * t4.w;        \
        _Pragma("unroll")                                                    \
        for (int i_ = 0; i_ < 6; i_++) {                                     \
            const float4 f_ =                                                \
                *(const float4*)(tf + (1 + i_) * ROWBYTES + (JB));           \
            ai[i_]     += b0.x * f_.x + b0.y * f_.y                          \
                        + b0.z * f_.z + b0.w * f_.w;                         \
            ai[6 + i_] += b1.x * f_.x + b1.y * f_.y                          \
                        + b1.z * f_.z + b1.w * f_.w;                         \
        }                                                                    \
    } while (0)

// stage {pu, iv[0..5]} for position Q into SLOT (7 ints)
#define STAGE_IDX(Q, SLOT)                                                   \
    do {                                                                     \
        if (tid < 7) {                                                       \
            const int ps_ = ((Q) < NPOS) ? (Q) : (NPOS - 1);                 \
            (SLOT)[tid] = (tid == 0) ? pos_u[ps_]                            \
                                     : info_v[ps_ * 6 + (tid - 1)];          \
        }                                                                    \
    } while (0)

// issue 525 cp.async 16B copies of the 7 shared rows into stage BUF
#define PRODUCE(BUF, SLOT)                                                   \
    do {                                                                     \
        const unsigned dbase_ = sbase + (unsigned)(BUF) * SHBUF;             \
        _Pragma("unroll")                                                    \
        for (int k_ = 0; k_ < 4; k_++) {                                     \
            const int n_ = tid + k_ * THREADS;                               \
            if (n_ < NCPY) {                                                 \
                const int row_ = n_ / 75;                                    \
                const int col_ = n_ - row_ * 75;                             \
                const long idx_ = (SLOT)[row_];                              \
                const char* src_ = ((row_ == 0) ? Wout_b : Win_b)            \
                                 + idx_ * ROWBYTES + col_ * 16;              \
                CP_ASYNC16(dbase_ + row_ * ROWBYTES + col_ * 16, src_);      \
            }                                                                \
        }                                                                    \
    } while (0)

// scattered 16-value warp reduction (31 shfl) + in-place loss term.
__device__ __forceinline__ float reduce_eval(
    float sc0, float sc1, const float* ai, int lane,
    float t_pre, float t_sgn, float t_wt)
{
    float v0[8], v1[4], v2[2], v3;
    {
        float a, b;
        a = sc0   + __shfl_xor_sync(0xffffffffu, sc0,   16);
        b = ai[6] + __shfl_xor_sync(0xffffffffu, ai[6], 16);
        v0[0] = (lane & 16) ? b : a;
        a = sc1   + __shfl_xor_sync(0xffffffffu, sc1,   16);
        b = ai[7] + __shfl_xor_sync(0xffffffffu, ai[7], 16);
        v0[1] = (lane & 16) ? b : a;
#pragma unroll
        for (int q = 0; q < 4; q++) {
            a = ai[q]     + __shfl_xor_sync(0xffffffffu, ai[q],     16);
            b = ai[q + 8] + __shfl_xor_sync(0xffffffffu, ai[q + 8], 16);
            v0[2 + q] = (lane & 16) ? b : a;
        }
        a = ai[4] + __shfl_xor_sync(0xffffffffu, ai[4], 16);
        v0[6] = (lane & 16) ? 0.f : a;
        a = ai[5] + __shfl_xor_sync(0xffffffffu, ai[5], 16);
        v0[7] = (lane & 16) ? 0.f : a;
    }
#pragma unroll
    for (int q = 0; q < 4; q++) {
        const float a = v0[q]     + __shfl_xor_sync(0xffffffffu, v0[q],     8);
        const float b = v0[q + 4] + __shfl_xor_sync(0xffffffffu, v0[q + 4], 8);
        v1[q] = (lane & 8) ? b : a;
    }
#pragma unroll
    for (int q = 0; q < 2; q++) {
        const float a = v1[q]     + __shfl_xor_sync(0xffffffffu, v1[q],     4);
        const float b = v1[q + 2] + __shfl_xor_sync(0xffffffffu, v1[q + 2], 4);
        v2[q] = (lane & 4) ? b : a;
    }
    {
        const float a = v2[0] + __shfl_xor_sync(0xffffffffu, v2[0], 2);
        const float b = v2[1] + __shfl_xor_sync(0xffffffffu, v2[1], 2);
        v3 = (lane & 2) ? b : a;
    }
    v3 += __shfl_xor_sync(0xffffffffu, v3, 1);

    const float x = fminf(fmaxf(v3 * t_pre, -10.f), 10.f) * t_sgn;
    return __logf(1.f + __expf(-x)) * t_wt;
}

__global__ __launch_bounds__(THREADS, 5) void hg2vec_fused(
    const int*   __restrict__ pos_u,
    const int*   __restrict__ pos_v,
    const int*   __restrict__ info_v,
    const float* __restrict__ W_in,
    const float* __restrict__ W_out,
    const float* __restrict__ cmask,
    const float* __restrict__ sig_mask,
    const float* __restrict__ score_mask,
    float*       __restrict__ out)
{
    __shared__ __align__(16) char tile[2][SHBUF];
    __shared__ int   idxs[2][8];
    __shared__ float wloss[5];
    __shared__ bool  amLast;

    const int tid  = threadIdx.x;
    const int w    = tid >> 5;
    const int lane = tid & 31;
    const unsigned sbase = (unsigned)__cvta_generic_to_shared(&tile[0][0]);

    const char* __restrict__ Win_b  = (const char*)W_in;
    const char* __restrict__ Wout_b = (const char*)W_out;

    // ---- per-lane term coefficients; value index k = lane>>1 ----
    const int kk = lane >> 1;
    float t_pre = 1.f, t_sgn = 1.f, t_wt = 0.f;
    if (((lane & 1) == 0) && kk < 14) {
        if (kk < 2) { t_pre = cmask[w * 2 + kk]; t_sgn = 1.f; t_wt = 1.f; }
        else {
            const int i = (kk - 2) % 6;
            t_sgn = sig_mask[i];
            t_wt  = score_mask[i];
        }
    }

    const unsigned jb0 = (unsigned)lane * 16u;
    const unsigned jb1 = jb0 + 512u;
    const unsigned jb2 = jb0 + 1024u;   // lanes 0..10 only

    float acc_loss = 0.f;
    int p   = blockIdx.x;
    int cur = 0;

    // ---- prime: shared-row tile 0 for p, idx slot 1 for p+GRID ----
    STAGE_IDX(p, idxs[0]);
    __syncthreads();
    PRODUCE(0, idxs[0]);
    CP_COMMIT();
    STAGE_IDX(p + GRID, idxs[1]);

    // private-row offsets + chunk0 preload for p
    unsigned pvo0 = (unsigned)pos_v[p * 10 + w * 2 + 0] * ROWBYTES;
    unsigned pvo1 = (unsigned)pos_v[p * 10 + w * 2 + 1] * ROWBYTES;
    float4 a0, a1, b0, b1;
    AB_LOAD(jb0);

    __syncthreads();            // idxs[1] visible before first loop iteration

    while (p < NPOS) {
        const int pn = p + GRID;

        // ---- producer: shared rows of pn into the other stage ----
        if (pn < NPOS) {
            PRODUCE(cur ^ 1, idxs[cur ^ 1]);
            CP_COMMIT();
            STAGE_IDX(pn + GRID, idxs[cur]);   // p's slot is free now
            CP_WAIT1();                        // stage(cur) fully arrived
        } else {
            CP_WAIT0();
        }
        __syncthreads();                       // tile[cur] + staged idx visible

        // ---- consumer: position p ----
        {
            const char* tf = tile[cur];
            float sc0 = 0.f, sc1 = 0.f;
            float ai[12];
#pragma unroll
            for (int q = 0; q < 12; q++) ai[q] = 0.f;

            // chunk 0: a/b preloaded
            TF_CHUNK(jb0);
            // chunk 1
            AB_LOAD(jb1);
            TF_CHUNK(jb1);
            // chunk 2 (lanes 0..10)
            if (lane < 11) AB_LOAD(jb2);

            // offsets dead after chunk2 issue: load next position's directly
            const int ps = (pn < NPOS) ? pn : 0;
            pvo0 = (unsigned)pos_v[ps * 10 + w * 2 + 0] * ROWBYTES;
            pvo1 = (unsigned)pos_v[ps * 10 + w * 2 + 1] * ROWBYTES;

            if (lane < 11) TF_CHUNK(jb2);

            // preload next position's private chunk0 (in flight over butterfly)
            AB_LOAD(jb0);

            acc_loss += reduce_eval(sc0, sc1, ai, lane, t_pre, t_sgn, t_wt);
        }

        __syncthreads();        // all warps done with tile[cur] before refill
        cur ^= 1;
        p = pn;
    }

    // ---- block reduction ----
#pragma unroll
    for (int off = 16; off; off >>= 1)
        acc_loss += __shfl_xor_sync(0xffffffffu, acc_loss, off);
    if (lane == 0) wloss[w] = acc_loss;
    __syncthreads();

    if (tid == 0) {
        float s = wloss[0] + wloss[1] + wloss[2] + wloss[3] + wloss[4];
        g_partial[blockIdx.x] = s;
        __threadfence();
        unsigned t = atomicAdd(&g_ticket, 1u);
        amLast = (t == GRID - 1);
    }
    __syncthreads();

    // ---- last block: deterministic fixed-order final sum ----
    if (amLast) {
        __shared__ float fs[THREADS];
        float v = 0.f;
        for (int i = tid; i < GRID; i += THREADS)
            v += __ldcg(&g_partial[i]);
        fs[tid] = v;
        __syncthreads();
#pragma unroll
        for (int st = 128; st; st >>= 1) {
            if (tid < st && tid + st < THREADS)
                fs[tid] += fs[tid + st];
            __syncthreads();
        }
        if (tid == 0) {
            out[0] = fs[0];
            g_ticket = 0;            // reset for next graph replay
            __threadfence();
        }
    }
}

extern "C" void kernel_launch(void* const* d_in, const int* in_sizes, int n_in,
                              void* d_out, int out_size)
{
    const int*   pos_u  = (const int*)  d_in[0];
    const int*   pos_v  = (const int*)  d_in[1];
    const int*   info_v = (const int*)  d_in[2];
    const float* W_in   = (const float*)d_in[3];
    const float* W_out  = (const float*)d_in[4];
    const float* cmask  = (const float*)d_in[5];
    const float* sigm   = (const float*)d_in[6];
    const float* smask  = (const float*)d_in[7];

    hg2vec_fused<<<GRID, THREADS>>>(pos_u, pos_v, info_v, W_in, W_out,
                                    cmask, sigm, smask, (float*)d_out);
}